// round 6
// baseline (speedup 1.0000x reference)
#include <cuda_runtime.h>

#define DEV_INLINE __device__ __forceinline__
typedef unsigned long long u64;

static constexpr int V  = 32000;
static constexpr int H  = 512;
static constexpr int Bz = 64;
static constexpr int S  = 128;
static constexpr int H2 = 1024;
static constexpr int G4 = 2048;
static constexpr int G8 = 4096;
static constexpr int R  = S * Bz;

// ---------------- scratch ---------------------------------------------------
__device__ float g_X   [R * H];
__device__ float g_GF  [R * G4];
__device__ float g_GB  [R * G4];
__device__ float g_XIN [R * H2];          // row-major, operand of phase D
__device__ float g_XINT[R * H2];          // per t transposed: [t][k][b]
__device__ float g_G1  [R * G8];
__device__ float g_H0T [2 * H * Bz];      // transposed h0f|h0b
__device__ float g_H1T [2 * H2 * Bz];     // ping-pong transposed
__device__ float g_H2T [2 * H2 * Bz];
__device__ float g_H2R [Bz * H2];         // final h2 row-major
__device__ unsigned g_bar0, g_bar1;

// ---------------- helpers ---------------------------------------------------
DEV_INLINE u64 pk2(float x, float y) {
    u64 r; asm("mov.b64 %0, {%1, %2};" : "=l"(r) : "f"(x), "f"(y)); return r;
}
DEV_INLINE float2 upk2(u64 v) {
    float2 r; asm("mov.b64 {%0, %1}, %2;" : "=f"(r.x), "=f"(r.y) : "l"(v)); return r;
}
#define FMA2(d, a, b) asm("fma.rn.f32x2 %0, %1, %2, %0;" : "+l"(d) : "l"(a), "l"(b))
DEV_INLINE float sigf(float x) { return 1.f / (1.f + expf(-x)); }
DEV_INLINE float4 ldcg4(const float* p) { return __ldcg((const float4*)p); }

DEV_INLINE void gbar(unsigned* cnt, unsigned target) {
    __threadfence();
    __syncthreads();
    if (threadIdx.x == 0) {
        atomicAdd(cnt, 1u);
        while (atomicAdd(cnt, 0u) < target) __nanosleep(64);
    }
    __syncthreads();
}

// ---------------- embedding gather ------------------------------------------
__global__ void k_embed(const int* __restrict__ x, const float* __restrict__ emb) {
    int r = blockIdx.x;
    int tok = x[r];
    float4 v = make_float4(0.f, 0.f, 0.f, 0.f);
    if (tok != 0) v = *(const float4*)(emb + (size_t)tok * H + threadIdx.x * 4);
    *(float4*)(g_X + (size_t)r * H + threadIdx.x * 4) = v;
}

// ---------------- init: transpose states, zero barriers ----------------------
__global__ void k_init(const float* __restrict__ h01, const float* __restrict__ h02,
                       const float* __restrict__ h0f, const float* __restrict__ h0b) {
    int i = blockIdx.x * blockDim.x + threadIdx.x;   // 768*256 = 196608
    if (i == 0) { g_bar0 = 0u; g_bar1 = 0u; }
    if (i < 65536) {
        int b = i >> 10, k = i & 1023;
        g_H1T[k * Bz + b] = h01[i];
    } else if (i < 131072) {
        int j = i - 65536, b = j >> 10, k = j & 1023;
        g_H2T[k * Bz + b] = h02[j];
    } else {
        int j = i - 131072, d = j >> 15, r = j & 32767;
        int b = r >> 9, k = r & 511;
        g_H0T[d * (H * Bz) + k * Bz + b] = (d ? h0b : h0f)[r];
    }
}

// ---------------- big GEMM, 128x128 tile, dup-A smem ------------------------
// C[M,N] = A[M,K] @ W[N,K]^T + b1 (+ b2). 256 thr, 8x8 outputs per thread.
__global__ void __launch_bounds__(256) k_gemm2(
        const float* __restrict__ A, const float* __restrict__ Wt,
        const float* __restrict__ b1, const float* __restrict__ b2,
        float* __restrict__ C, int K, int N) {
    __shared__ float As2[16][264];   // duplicated m: [k][2m]=[k][2m+1]=A
    __shared__ float Bs [16][132];
    const int tid = threadIdx.x;
    const int tx = tid & 15, ty = tid >> 4;
    const int bm = blockIdx.y * 128, bn = blockIdx.x * 128;

    u64 acc[8][4];
#pragma unroll
    for (int r = 0; r < 8; r++)
#pragma unroll
        for (int c = 0; c < 4; c++) acc[r][c] = 0ull;

    for (int k0 = 0; k0 < K; k0 += 16) {
#pragma unroll
        for (int p = 0; p < 2; p++) {
            int i = p * 256 + tid;
            int m = i >> 2, kq = (i & 3) * 4;
            float4 v = *(const float4*)(A + (size_t)(bm + m) * K + k0 + kq);
            *(float2*)&As2[kq + 0][2 * m] = make_float2(v.x, v.x);
            *(float2*)&As2[kq + 1][2 * m] = make_float2(v.y, v.y);
            *(float2*)&As2[kq + 2][2 * m] = make_float2(v.z, v.z);
            *(float2*)&As2[kq + 3][2 * m] = make_float2(v.w, v.w);
        }
#pragma unroll
        for (int p = 0; p < 2; p++) {
            int i = p * 256 + tid;
            int n = i >> 2, kq = (i & 3) * 4;
            float4 v = *(const float4*)(Wt + (size_t)(bn + n) * K + k0 + kq);
            Bs[kq + 0][n] = v.x; Bs[kq + 1][n] = v.y;
            Bs[kq + 2][n] = v.z; Bs[kq + 3][n] = v.w;
        }
        __syncthreads();
#pragma unroll
        for (int kk = 0; kk < 16; kk++) {
            const ulonglong2* ap = (const ulonglong2*)&As2[kk][ty * 16];
            ulonglong2 a01 = ap[0], a23 = ap[1], a45 = ap[2], a67 = ap[3];
            const u64* bp = (const u64*)&Bs[kk][tx * 8];
            u64 b0 = bp[0], b1v = bp[1], b2v = bp[2], b3v = bp[3];
            u64 A8[8] = {a01.x, a01.y, a23.x, a23.y, a45.x, a45.y, a67.x, a67.y};
#pragma unroll
            for (int r = 0; r < 8; r++) {
                FMA2(acc[r][0], A8[r], b0);
                FMA2(acc[r][1], A8[r], b1v);
                FMA2(acc[r][2], A8[r], b2v);
                FMA2(acc[r][3], A8[r], b3v);
            }
        }
        __syncthreads();
    }
    const int col = bn + tx * 8;
    float bb[8];
#pragma unroll
    for (int c = 0; c < 8; c++)
        bb[c] = b1[col + c] + (b2 ? b2[col + c] : 0.f);
#pragma unroll
    for (int r = 0; r < 8; r++) {
        float* crow = C + (size_t)(bm + ty * 8 + r) * N + col;
        float2 v0 = upk2(acc[r][0]), v1 = upk2(acc[r][1]);
        float2 v2 = upk2(acc[r][2]), v3 = upk2(acc[r][3]);
        *(float4*)(crow + 0) = make_float4(v0.x + bb[0], v0.y + bb[1], v1.x + bb[2], v1.y + bb[3]);
        *(float4*)(crow + 4) = make_float4(v2.x + bb[4], v2.y + bb[5], v3.x + bb[6], v3.y + bb[7]);
    }
}

// ---------------- small-M GEMM for logits (proven) ---------------------------
template <int BM>
__global__ void k_gemm_bias(const float* __restrict__ A, const float* __restrict__ Wt,
                            const float* __restrict__ b1, const float* __restrict__ b2,
                            float* __restrict__ C, int K, int N) {
    constexpr int BN = 64, BK = 16, RPT = BM / 16;
    __shared__ float As[BK][BM + 4];
    __shared__ float Bs[BK][BN + 4];
    const int tid = threadIdx.x;
    const int bm = blockIdx.y * BM, bn = blockIdx.x * BN;
    const int tx = tid & 15, ty = tid >> 4;
    u64 acc[RPT][2];
#pragma unroll
    for (int r = 0; r < RPT; r++) { acc[r][0] = 0ull; acc[r][1] = 0ull; }
    for (int k0 = 0; k0 < K; k0 += BK) {
#pragma unroll
        for (int i = tid; i < BM * 4; i += 256) {
            int m = i >> 2, kq = i & 3;
            float4 v = *(const float4*)(A + (size_t)(bm + m) * K + k0 + kq * 4);
            As[kq * 4 + 0][m] = v.x; As[kq * 4 + 1][m] = v.y;
            As[kq * 4 + 2][m] = v.z; As[kq * 4 + 3][m] = v.w;
        }
        {
            int n = tid >> 2, kq = tid & 3;
            float4 v = *(const float4*)(Wt + (size_t)(bn + n) * K + k0 + kq * 4);
            Bs[kq * 4 + 0][n] = v.x; Bs[kq * 4 + 1][n] = v.y;
            Bs[kq * 4 + 2][n] = v.z; Bs[kq * 4 + 3][n] = v.w;
        }
        __syncthreads();
#pragma unroll
        for (int kk = 0; kk < BK; kk++) {
            float2 bv0 = *(const float2*)&Bs[kk][tx * 4];
            float2 bv1 = *(const float2*)&Bs[kk][tx * 4 + 2];
            u64 bp0 = pk2(bv0.x, bv0.y), bp1 = pk2(bv1.x, bv1.y);
#pragma unroll
            for (int r = 0; r < RPT; r++) {
                float a = As[kk][ty * RPT + r];
                u64 ap = pk2(a, a);
                FMA2(acc[r][0], ap, bp0);
                FMA2(acc[r][1], ap, bp1);
            }
        }
        __syncthreads();
    }
    const int ncol = bn + tx * 4;
    float bb0 = b1[ncol + 0] + (b2 ? b2[ncol + 0] : 0.f);
    float bb1 = b1[ncol + 1] + (b2 ? b2[ncol + 1] : 0.f);
    float bb2 = b1[ncol + 2] + (b2 ? b2[ncol + 2] : 0.f);
    float bb3 = b1[ncol + 3] + (b2 ? b2[ncol + 3] : 0.f);
#pragma unroll
    for (int r = 0; r < RPT; r++) {
        float2 v0 = upk2(acc[r][0]);
        float2 v1 = upk2(acc[r][1]);
        float4 o = make_float4(v0.x + bb0, v0.y + bb1, v1.x + bb2, v1.y + bb3);
        *(float4*)(C + (size_t)(bm + ty * RPT + r) * N + ncol) = o;
    }
}

// ---------------- persistent layer-0 ----------------------------------------
// 128 blocks = 64 j-slices x 2 dirs; W resident in SMEM; c in registers.
// SMEM: Ws[512][32] + dup-h double buffer Hs2[2][64][132].
__global__ void __launch_bounds__(256, 1) k_l0_persist(
        const float* __restrict__ c0f, const float* __restrict__ c0b,
        const float* __restrict__ whh_f, const float* __restrict__ whh_b) {
    extern __shared__ float sm[];
    float* Ws  = sm;                     // [512][32]
    float* Hs2 = sm + 512 * 32;          // [2][64][132] duplicated b
    const int tid = threadIdx.x;
    const int dir = blockIdx.x >> 6;
    const int j0  = (blockIdx.x & 63) * 8;
    const int tx = tid & 7, r0 = (tid >> 3) * 2;
    const int jg = j0 + tx;
    const float* Whh  = dir ? whh_b : whh_f;
    const float* preB = dir ? g_GB  : g_GF;
    const float* c0   = dir ? c0b   : c0f;

    {   // cache W slice once: Ws[k][gj], gj = j*4 + gate
        const int gj = tid & 31, kq = tid >> 5;
        const float* wr = Whh + (size_t)((gj & 3) * H + j0 + (gj >> 2)) * H + kq * 64;
#pragma unroll
        for (int i = 0; i < 16; i++) {
            float4 v = __ldg((const float4*)(wr + i * 4));
            int k = kq * 64 + i * 4;
            Ws[(k + 0) * 32 + gj] = v.x; Ws[(k + 1) * 32 + gj] = v.y;
            Ws[(k + 2) * 32 + gj] = v.z; Ws[(k + 3) * 32 + gj] = v.w;
        }
    }
    float cst[2] = { c0[(r0 + 0) * H + jg], c0[(r0 + 1) * H + jg] };
    __syncthreads();

    for (int t = 0; t < S; t++) {
        const float* hT = (t == 0) ? (g_H0T + dir * (H * Bz))
                                   : (g_XINT + ((size_t)(t - 1) * H2 + dir * H) * Bz);
        const float* pre = preB + (size_t)(dir ? (S - 1 - t) : t) * Bz * G4;
        // acc init = precomputed input-side gates (also hides their latency)
        u64 acc[2][2];
#pragma unroll
        for (int r = 0; r < 2; r++) {
            const float* pb = pre + (size_t)(r0 + r) * G4;
            acc[r][0] = pk2(__ldg(pb + 0 * H + jg), __ldg(pb + 1 * H + jg));
            acc[r][1] = pk2(__ldg(pb + 2 * H + jg), __ldg(pb + 3 * H + jg));
        }
        float4 hv[4];
#pragma unroll
        for (int i = 0; i < 4; i++) hv[i] = ldcg4(hT + (i * 256 + tid) * 4);
#pragma unroll
        for (int i = 0; i < 4; i++) {
            int f4 = i * 256 + tid;
            float* d = &Hs2[(f4 >> 4) * 132 + (f4 & 15) * 8];
            *(float2*)(d + 0) = make_float2(hv[i].x, hv[i].x);
            *(float2*)(d + 2) = make_float2(hv[i].y, hv[i].y);
            *(float2*)(d + 4) = make_float2(hv[i].z, hv[i].z);
            *(float2*)(d + 6) = make_float2(hv[i].w, hv[i].w);
        }
        __syncthreads();
        for (int kt = 0; kt < 8; kt++) {
            int cur = kt & 1;
            if (kt < 7) {
#pragma unroll
                for (int i = 0; i < 4; i++)
                    hv[i] = ldcg4(hT + ((kt + 1) * 1024 + i * 256 + tid) * 4);
            }
            const float* Hc = Hs2 + cur * (64 * 132);
            const float* Wk = Ws + kt * 64 * 32;
#pragma unroll 16
            for (int kk = 0; kk < 64; kk++) {
                ulonglong2 a = *(const ulonglong2*)&Hc[kk * 132 + 2 * r0];
                ulonglong2 w = *(const ulonglong2*)&Wk[kk * 32 + tx * 4];
                FMA2(acc[0][0], a.x, w.x); FMA2(acc[0][1], a.x, w.y);
                FMA2(acc[1][0], a.y, w.x); FMA2(acc[1][1], a.y, w.y);
            }
            if (kt < 7) {
                float* Hn = Hs2 + (cur ^ 1) * (64 * 132);
#pragma unroll
                for (int i = 0; i < 4; i++) {
                    int f4 = i * 256 + tid;
                    float* d = &Hn[(f4 >> 4) * 132 + (f4 & 15) * 8];
                    *(float2*)(d + 0) = make_float2(hv[i].x, hv[i].x);
                    *(float2*)(d + 2) = make_float2(hv[i].y, hv[i].y);
                    *(float2*)(d + 4) = make_float2(hv[i].z, hv[i].z);
                    *(float2*)(d + 6) = make_float2(hv[i].w, hv[i].w);
                }
            }
            __syncthreads();
        }
#pragma unroll
        for (int r = 0; r < 2; r++) {
            int b = r0 + r;
            float2 if_ = upk2(acc[r][0]);
            float2 go_ = upk2(acc[r][1]);
            float c2 = sigf(if_.y) * cst[r] + sigf(if_.x) * tanhf(go_.x);
            cst[r] = c2;
            float h = sigf(go_.y) * tanhf(c2);
            g_XIN [((size_t)t * Bz + b) * H2 + dir * H + jg] = h;
            g_XINT[((size_t)t * H2 + dir * H + jg) * Bz + b] = h;
        }
        gbar(&g_bar0, 128u * (t + 1));
    }
}

// ---------------- layer-1 streaming tile GEMM (K=1024) ------------------------
DEV_INLINE void l1_gemm(const float* __restrict__ hT, const float* __restrict__ W,
                        int j0, int tid, u64 acc[2][2], float* Hs2, float* Ws) {
    const int tx = tid & 7, r0 = (tid >> 3) * 2;
    const int gj = tid & 31, kq = tid >> 5;
    const float* wrow = W + (size_t)((gj & 3) * H2 + j0 + (gj >> 2)) * H2 + kq * 8;
    float4 hv[4], wv[2];
#pragma unroll
    for (int i = 0; i < 4; i++) hv[i] = ldcg4(hT + (i * 256 + tid) * 4);
#pragma unroll
    for (int i = 0; i < 2; i++) wv[i] = __ldg((const float4*)(wrow + i * 4));
#pragma unroll
    for (int i = 0; i < 4; i++) {
        int f4 = i * 256 + tid;
        float* d = &Hs2[(f4 >> 4) * 132 + (f4 & 15) * 8];
        *(float2*)(d + 0) = make_float2(hv[i].x, hv[i].x);
        *(float2*)(d + 2) = make_float2(hv[i].y, hv[i].y);
        *(float2*)(d + 4) = make_float2(hv[i].z, hv[i].z);
        *(float2*)(d + 6) = make_float2(hv[i].w, hv[i].w);
    }
#pragma unroll
    for (int i = 0; i < 2; i++) {
        int k = kq * 8 + i * 4;
        Ws[(k + 0) * 32 + gj] = wv[i].x; Ws[(k + 1) * 32 + gj] = wv[i].y;
        Ws[(k + 2) * 32 + gj] = wv[i].z; Ws[(k + 3) * 32 + gj] = wv[i].w;
    }
    __syncthreads();
    for (int kt = 0; kt < 16; kt++) {
        int cur = kt & 1;
        if (kt < 15) {
#pragma unroll
            for (int i = 0; i < 4; i++)
                hv[i] = ldcg4(hT + ((kt + 1) * 1024 + i * 256 + tid) * 4);
#pragma unroll
            for (int i = 0; i < 2; i++)
                wv[i] = __ldg((const float4*)(wrow + (kt + 1) * 64 + i * 4));
        }
        const float* Hc = Hs2 + cur * (64 * 132);
        const float* Wc = Ws + cur * (64 * 32);
#pragma unroll 16
        for (int kk = 0; kk < 64; kk++) {
            ulonglong2 a = *(const ulonglong2*)&Hc[kk * 132 + 2 * r0];
            ulonglong2 w = *(const ulonglong2*)&Wc[kk * 32 + tx * 4];
            FMA2(acc[0][0], a.x, w.x); FMA2(acc[0][1], a.x, w.y);
            FMA2(acc[1][0], a.y, w.x); FMA2(acc[1][1], a.y, w.y);
        }
        if (kt < 15) {
            float* Hn = Hs2 + (cur ^ 1) * (64 * 132);
            float* Wn = Ws + (cur ^ 1) * (64 * 32);
#pragma unroll
            for (int i = 0; i < 4; i++) {
                int f4 = i * 256 + tid;
                float* d = &Hn[(f4 >> 4) * 132 + (f4 & 15) * 8];
                *(float2*)(d + 0) = make_float2(hv[i].x, hv[i].x);
                *(float2*)(d + 2) = make_float2(hv[i].y, hv[i].y);
                *(float2*)(d + 4) = make_float2(hv[i].z, hv[i].z);
                *(float2*)(d + 6) = make_float2(hv[i].w, hv[i].w);
            }
#pragma unroll
            for (int i = 0; i < 2; i++) {
                int k = kq * 8 + i * 4;
                Wn[(k + 0) * 32 + gj] = wv[i].x; Wn[(k + 1) * 32 + gj] = wv[i].y;
                Wn[(k + 2) * 32 + gj] = wv[i].z; Wn[(k + 3) * 32 + gj] = wv[i].w;
            }
        }
        __syncthreads();
    }
}

// ---------------- persistent layer-1 -----------------------------------------
__global__ void __launch_bounds__(256, 1) k_l1_persist(
        const float* __restrict__ c02,
        const float* __restrict__ whh1, const float* __restrict__ wih2,
        const float* __restrict__ whh2,
        const float* __restrict__ bih2, const float* __restrict__ bhh2) {
    extern __shared__ float sm[];
    float* Ws  = sm;                     // [2][64][32]
    float* Hs2 = sm + 2 * 64 * 32;       // [2][64][132]
    const int tid = threadIdx.x;
    const int j0 = blockIdx.x * 8;
    const int tx = tid & 7, r0 = (tid >> 3) * 2;
    const int jg = j0 + tx;

    float c2[2] = { c02[(r0 + 0) * H2 + jg], c02[(r0 + 1) * H2 + jg] };
    float bs[4];
#pragma unroll
    for (int g = 0; g < 4; g++) bs[g] = bih2[g * H2 + jg] + bhh2[g * H2 + jg];

    unsigned bt = 0;
    for (int t = 0; t < S; t++) {
        int p = t & 1;
        const float* h1prev = g_H1T + p * (H2 * Bz);
        float*       h1out  = g_H1T + (p ^ 1) * (H2 * Bz);
        const float* h2prev = g_H2T + p * (H2 * Bz);
        float*       h2out  = g_H2T + (p ^ 1) * (H2 * Bz);

        // ---- lstm1: whh1 @ h1prev; acc init = G1 precomputed gates ----
        const float* pre = g_G1 + (size_t)t * Bz * G8;
        u64 acc[2][2];
#pragma unroll
        for (int r = 0; r < 2; r++) {
            const float* pb = pre + (size_t)(r0 + r) * G8;
            acc[r][0] = pk2(__ldg(pb + 0 * H2 + jg), __ldg(pb + 1 * H2 + jg));
            acc[r][1] = pk2(__ldg(pb + 2 * H2 + jg), __ldg(pb + 3 * H2 + jg));
        }
        l1_gemm(h1prev, whh1, j0, tid, acc, Hs2, Ws);
#pragma unroll
        for (int r = 0; r < 2; r++) {
            int b = r0 + r;
            float2 if_ = upk2(acc[r][0]);
            float2 go_ = upk2(acc[r][1]);
            float cc = sigf(if_.y) * c2[r] + sigf(if_.x) * tanhf(go_.x);
            h1out[(size_t)jg * Bz + b] = sigf(go_.y) * tanhf(cc);
        }
        // ---- lstm2 part A: whh2 @ h2prev; acc init = combined biases ----
#pragma unroll
        for (int r = 0; r < 2; r++) {
            acc[r][0] = pk2(bs[0], bs[1]);
            acc[r][1] = pk2(bs[2], bs[3]);
        }
        l1_gemm(h2prev, whh2, j0, tid, acc, Hs2, Ws);
        bt += 128; gbar(&g_bar1, bt);            // publish h1out
        // ---- lstm2 part B: wih2 @ h1new ----
        l1_gemm(h1out, wih2, j0, tid, acc, Hs2, Ws);
#pragma unroll
        for (int r = 0; r < 2; r++) {
            int b = r0 + r;
            float2 if_ = upk2(acc[r][0]);
            float2 go_ = upk2(acc[r][1]);
            float cn = sigf(if_.y) * c2[r] + sigf(if_.x) * tanhf(go_.x);
            c2[r] = cn;
            float h2v = sigf(go_.y) * tanhf(cn);
            h2out[(size_t)jg * Bz + b] = h2v;
            if (t == S - 1) g_H2R[(size_t)b * H2 + jg] = h2v;
        }
        bt += 128; gbar(&g_bar1, bt);            // publish h2out
    }
}

// ---------------- launch -----------------------------------------------------
extern "C" void kernel_launch(void* const* d_in, const int* in_sizes, int n_in,
                              void* d_out, int out_size) {
    const int*   x     = (const int*)  d_in[0];
    const float* emb   = (const float*)d_in[1];
    const float* h0f   = (const float*)d_in[2];
    const float* c0f   = (const float*)d_in[3];
    const float* h0b   = (const float*)d_in[4];
    const float* c0b   = (const float*)d_in[5];
    const float* h01   = (const float*)d_in[6];
    const float* h02   = (const float*)d_in[7];
    const float* c02   = (const float*)d_in[8];
    const float* wih_f = (const float*)d_in[9];
    const float* whh_f = (const float*)d_in[10];
    const float* bih_f = (const float*)d_in[11];
    const float* bhh_f = (const float*)d_in[12];
    const float* wih_b = (const float*)d_in[13];
    const float* whh_b = (const float*)d_in[14];
    const float* bih_b = (const float*)d_in[15];
    const float* bhh_b = (const float*)d_in[16];
    const float* wih1  = (const float*)d_in[17];
    const float* whh1  = (const float*)d_in[18];
    const float* bih1  = (const float*)d_in[19];
    const float* bhh1  = (const float*)d_in[20];
    const float* wih2  = (const float*)d_in[21];
    const float* whh2  = (const float*)d_in[22];
    const float* bih2  = (const float*)d_in[23];
    const float* bhh2  = (const float*)d_in[24];
    const float* wlin  = (const float*)d_in[25];
    const float* blin  = (const float*)d_in[26];
    float* out = (float*)d_out;

    float *pX, *pGF, *pGB, *pXIN, *pG1, *pH2R;
    cudaGetSymbolAddress((void**)&pX,   g_X);
    cudaGetSymbolAddress((void**)&pGF,  g_GF);
    cudaGetSymbolAddress((void**)&pGB,  g_GB);
    cudaGetSymbolAddress((void**)&pXIN, g_XIN);
    cudaGetSymbolAddress((void**)&pG1,  g_G1);
    cudaGetSymbolAddress((void**)&pH2R, g_H2R);

    const int L0_SM = (512 * 32 + 2 * 64 * 132) * 4;         // 133120 B
    const int L1_SM = (2 * 64 * 32 + 2 * 64 * 132) * 4;      // 83968 B
    cudaFuncSetAttribute(k_l0_persist, cudaFuncAttributeMaxDynamicSharedMemorySize, L0_SM);
    cudaFuncSetAttribute(k_l1_persist, cudaFuncAttributeMaxDynamicSharedMemorySize, L1_SM);

    // A: gather + init (also zeroes barrier counters each replay)
    k_embed<<<R, 128>>>(x, emb);
    k_init<<<768, 256>>>(h01, h02, h0f, h0b);

    // B: hoisted input-side gate GEMMs for layer 0
    k_gemm2<<<dim3(G4 / 128, R / 128), 256>>>(pX, wih_f, bih_f, bhh_f, pGF, H, G4);
    k_gemm2<<<dim3(G4 / 128, R / 128), 256>>>(pX, wih_b, bih_b, bhh_b, pGB, H, G4);

    // C: persistent bidirectional layer-0 recurrence
    k_l0_persist<<<128, 256, L0_SM>>>(c0f, c0b, whh_f, whh_b);

    // D: hoisted input-side GEMM for lstm1
    k_gemm2<<<dim3(G8 / 128, R / 128), 256>>>(pXIN, wih1, bih1, bhh1, pG1, H2, G8);

    // E: persistent layer-1 recurrence
    k_l1_persist<<<128, 256, L1_SM>>>(c02, whh1, wih2, whh2, bih2, bhh2);

    // F: logits
    k_gemm_bias<64><<<dim3(V / 64, 1), 256>>>(pH2R, wlin, blin, nullptr, out, H2, V);
}

// round 7
// speedup vs baseline: 1.2098x; 1.2098x over previous
#include <cuda_runtime.h>

#define DEV_INLINE __device__ __forceinline__
typedef unsigned long long u64;

static constexpr int V  = 32000;
static constexpr int H  = 512;
static constexpr int Bz = 64;
static constexpr int S  = 128;
static constexpr int H2 = 1024;
static constexpr int G4 = 2048;
static constexpr int G8 = 4096;
static constexpr int R  = S * Bz;

// ---------------- scratch ---------------------------------------------------
__device__ float g_X   [R * H];
__device__ float g_GF  [R * G4];
__device__ float g_GB  [R * G4];
__device__ float g_XIN [R * H2];          // row-major, operand of phase D
__device__ float g_XINT[R * H2];          // per t transposed: [t][k][b]
__device__ float g_G1  [R * G8];
__device__ float g_H0T [2 * H * Bz];      // transposed h0f|h0b
__device__ float g_H1T [2 * H2 * Bz];     // ping-pong transposed
__device__ float g_H2T [2 * H2 * Bz];
__device__ float g_H2R [Bz * H2];         // final h2 row-major
__device__ unsigned g_bar0, g_bar1;

// ---------------- helpers ---------------------------------------------------
DEV_INLINE u64 pk2(float x, float y) {
    u64 r; asm("mov.b64 %0, {%1, %2};" : "=l"(r) : "f"(x), "f"(y)); return r;
}
DEV_INLINE float2 upk2(u64 v) {
    float2 r; asm("mov.b64 {%0, %1}, %2;" : "=f"(r.x), "=f"(r.y) : "l"(v)); return r;
}
#define FMA2(d, a, b) asm("fma.rn.f32x2 %0, %1, %2, %0;" : "+l"(d) : "l"(a), "l"(b))
DEV_INLINE float sigf(float x) { return 1.f / (1.f + expf(-x)); }
DEV_INLINE float4 ldcg4(const float* p) { return __ldcg((const float4*)p); }

DEV_INLINE void gbar(unsigned* cnt, unsigned target) {
    __threadfence();
    __syncthreads();
    if (threadIdx.x == 0) {
        atomicAdd(cnt, 1u);
        while (atomicAdd(cnt, 0u) < target) __nanosleep(64);
    }
    __syncthreads();
}

// ---------------- embedding gather ------------------------------------------
__global__ void k_embed(const int* __restrict__ x, const float* __restrict__ emb) {
    int r = blockIdx.x;
    int tok = x[r];
    float4 v = make_float4(0.f, 0.f, 0.f, 0.f);
    if (tok != 0) v = *(const float4*)(emb + (size_t)tok * H + threadIdx.x * 4);
    *(float4*)(g_X + (size_t)r * H + threadIdx.x * 4) = v;
}

// ---------------- init: transpose states, zero barriers ----------------------
__global__ void k_init(const float* __restrict__ h01, const float* __restrict__ h02,
                       const float* __restrict__ h0f, const float* __restrict__ h0b) {
    int i = blockIdx.x * blockDim.x + threadIdx.x;   // 768*256 = 196608
    if (i == 0) { g_bar0 = 0u; g_bar1 = 0u; }
    if (i < 65536) {
        int b = i >> 10, k = i & 1023;
        g_H1T[k * Bz + b] = h01[i];
    } else if (i < 131072) {
        int j = i - 65536, b = j >> 10, k = j & 1023;
        g_H2T[k * Bz + b] = h02[j];
    } else {
        int j = i - 131072, d = j >> 15, r = j & 32767;
        int b = r >> 9, k = r & 511;
        g_H0T[d * (H * Bz) + k * Bz + b] = (d ? h0b : h0f)[r];
    }
}

// ---------------- big batched GEMM (proven) ----------------------------------
template <int BM>
__global__ void k_gemm_bias(const float* __restrict__ A, const float* __restrict__ Wt,
                            const float* __restrict__ b1, const float* __restrict__ b2,
                            float* __restrict__ C, int K, int N) {
    constexpr int BN = 64, BK = 16, RPT = BM / 16;
    __shared__ float As[BK][BM + 4];
    __shared__ float Bs[BK][BN + 4];
    const int tid = threadIdx.x;
    const int bm = blockIdx.y * BM, bn = blockIdx.x * BN;
    const int tx = tid & 15, ty = tid >> 4;
    u64 acc[RPT][2];
#pragma unroll
    for (int r = 0; r < RPT; r++) { acc[r][0] = 0ull; acc[r][1] = 0ull; }
    for (int k0 = 0; k0 < K; k0 += BK) {
#pragma unroll
        for (int i = tid; i < BM * 4; i += 256) {
            int m = i >> 2, kq = i & 3;
            float4 v = *(const float4*)(A + (size_t)(bm + m) * K + k0 + kq * 4);
            As[kq * 4 + 0][m] = v.x; As[kq * 4 + 1][m] = v.y;
            As[kq * 4 + 2][m] = v.z; As[kq * 4 + 3][m] = v.w;
        }
        {
            int n = tid >> 2, kq = tid & 3;
            float4 v = *(const float4*)(Wt + (size_t)(bn + n) * K + k0 + kq * 4);
            Bs[kq * 4 + 0][n] = v.x; Bs[kq * 4 + 1][n] = v.y;
            Bs[kq * 4 + 2][n] = v.z; Bs[kq * 4 + 3][n] = v.w;
        }
        __syncthreads();
#pragma unroll
        for (int kk = 0; kk < BK; kk++) {
            float2 bv0 = *(const float2*)&Bs[kk][tx * 4];
            float2 bv1 = *(const float2*)&Bs[kk][tx * 4 + 2];
            u64 bp0 = pk2(bv0.x, bv0.y), bp1 = pk2(bv1.x, bv1.y);
#pragma unroll
            for (int r = 0; r < RPT; r++) {
                float a = As[kk][ty * RPT + r];
                u64 ap = pk2(a, a);
                FMA2(acc[r][0], ap, bp0);
                FMA2(acc[r][1], ap, bp1);
            }
        }
        __syncthreads();
    }
    const int ncol = bn + tx * 4;
    float bb0 = b1[ncol + 0] + (b2 ? b2[ncol + 0] : 0.f);
    float bb1 = b1[ncol + 1] + (b2 ? b2[ncol + 1] : 0.f);
    float bb2 = b1[ncol + 2] + (b2 ? b2[ncol + 2] : 0.f);
    float bb3 = b1[ncol + 3] + (b2 ? b2[ncol + 3] : 0.f);
#pragma unroll
    for (int r = 0; r < RPT; r++) {
        float2 v0 = upk2(acc[r][0]);
        float2 v1 = upk2(acc[r][1]);
        float4 o = make_float4(v0.x + bb0, v0.y + bb1, v1.x + bb2, v1.y + bb3);
        *(float4*)(C + (size_t)(bm + ty * RPT + r) * N + ncol) = o;
    }
}

// ---------------- persistent layer-0 ----------------------------------------
// 128 blocks = 64 j-slices x 2 dirs; W slice resident in SMEM; c in registers.
__global__ void __launch_bounds__(256, 1) k_l0_persist(
        const float* __restrict__ c0f, const float* __restrict__ c0b,
        const float* __restrict__ whh_f, const float* __restrict__ whh_b) {
    extern __shared__ float sm[];
    float* Ws = sm;                 // [512][32]
    float* Hs = sm + 512 * 32;      // [2][64][68]
    const int tid = threadIdx.x;
    const int dir = blockIdx.x >> 6;
    const int j0  = (blockIdx.x & 63) * 8;
    const int tx = tid & 7, r0 = (tid >> 3) * 2;
    const int jg = j0 + tx;
    const float* Whh  = dir ? whh_b : whh_f;
    const float* preB = dir ? g_GB  : g_GF;
    const float* c0   = dir ? c0b   : c0f;

    {   // cache W slice once: Ws[k][gj], gj = j*4 + gate
        const int gj = tid & 31, kq = tid >> 5;
        const float* wr = Whh + (size_t)((gj & 3) * H + j0 + (gj >> 2)) * H + kq * 64;
#pragma unroll
        for (int i = 0; i < 16; i++) {
            float4 v = __ldg((const float4*)(wr + i * 4));
            int k = kq * 64 + i * 4;
            Ws[(k + 0) * 32 + gj] = v.x; Ws[(k + 1) * 32 + gj] = v.y;
            Ws[(k + 2) * 32 + gj] = v.z; Ws[(k + 3) * 32 + gj] = v.w;
        }
    }
    float cst[2] = { c0[(r0 + 0) * H + jg], c0[(r0 + 1) * H + jg] };
    __syncthreads();

    for (int t = 0; t < S; t++) {
        const float* hT = (t == 0) ? (g_H0T + dir * (H * Bz))
                                   : (g_XINT + ((size_t)(t - 1) * H2 + dir * H) * Bz);
        u64 acc[2][2] = {{0ull, 0ull}, {0ull, 0ull}};
        float4 hv[4];
#pragma unroll
        for (int i = 0; i < 4; i++) hv[i] = ldcg4(hT + (i * 256 + tid) * 4);
#pragma unroll
        for (int i = 0; i < 4; i++) {
            int f4 = i * 256 + tid;
            *(float4*)&Hs[(f4 >> 4) * 68 + (f4 & 15) * 4] = hv[i];
        }
        __syncthreads();
        for (int kt = 0; kt < 8; kt++) {
            int cur = kt & 1;
            if (kt < 7) {
#pragma unroll
                for (int i = 0; i < 4; i++)
                    hv[i] = ldcg4(hT + ((kt + 1) * 1024 + i * 256 + tid) * 4);
            }
            const float* Hc = Hs + cur * (64 * 68);
            const float* Wk = Ws + kt * 64 * 32;
#pragma unroll 8
            for (int kk = 0; kk < 64; kk++) {
                float2 a = *(const float2*)&Hc[kk * 68 + r0];
                ulonglong2 w = *(const ulonglong2*)&Wk[kk * 32 + tx * 4];  // LDS.128
                u64 a0 = pk2(a.x, a.x), a1 = pk2(a.y, a.y);
                FMA2(acc[0][0], a0, w.x); FMA2(acc[0][1], a0, w.y);
                FMA2(acc[1][0], a1, w.x); FMA2(acc[1][1], a1, w.y);
            }
            if (kt < 7) {
                float* Hn = Hs + (cur ^ 1) * (64 * 68);
#pragma unroll
                for (int i = 0; i < 4; i++) {
                    int f4 = i * 256 + tid;
                    *(float4*)&Hn[(f4 >> 4) * 68 + (f4 & 15) * 4] = hv[i];
                }
            }
            __syncthreads();
        }
        // fused gate epilogue
        const float* pre = preB + (size_t)(dir ? (S - 1 - t) : t) * Bz * G4;
#pragma unroll
        for (int r = 0; r < 2; r++) {
            int b = r0 + r;
            float2 if_ = upk2(acc[r][0]);
            float2 go_ = upk2(acc[r][1]);
            const float* pb = pre + (size_t)b * G4;
            float gi = if_.x + pb[0 * H + jg];
            float gf = if_.y + pb[1 * H + jg];
            float gg = go_.x + pb[2 * H + jg];
            float go = go_.y + pb[3 * H + jg];
            float c2 = sigf(gf) * cst[r] + sigf(gi) * tanhf(gg);
            cst[r] = c2;
            float h = sigf(go) * tanhf(c2);
            g_XIN [((size_t)t * Bz + b) * H2 + dir * H + jg] = h;
            g_XINT[((size_t)t * H2 + dir * H + jg) * Bz + b] = h;
        }
        gbar(&g_bar0, 128u * (t + 1));
    }
}

// ---------------- layer-1 streaming tile GEMM (K=1024) ------------------------
DEV_INLINE void l1_gemm(const float* __restrict__ hT, const float* __restrict__ W,
                        int j0, int tid, u64 acc[2][2], float* Hs, float* Ws) {
    const int tx = tid & 7, r0 = (tid >> 3) * 2;
    const int gj = tid & 31, kq = tid >> 5;
    const float* wrow = W + (size_t)((gj & 3) * H2 + j0 + (gj >> 2)) * H2 + kq * 8;
    float4 hv[4], wv[2];
#pragma unroll
    for (int i = 0; i < 4; i++) hv[i] = ldcg4(hT + (i * 256 + tid) * 4);
#pragma unroll
    for (int i = 0; i < 2; i++) wv[i] = __ldg((const float4*)(wrow + i * 4));
#pragma unroll
    for (int i = 0; i < 4; i++) {
        int f4 = i * 256 + tid;
        *(float4*)&Hs[(f4 >> 4) * 68 + (f4 & 15) * 4] = hv[i];
    }
#pragma unroll
    for (int i = 0; i < 2; i++) {
        int k = kq * 8 + i * 4;
        Ws[(k + 0) * 32 + gj] = wv[i].x; Ws[(k + 1) * 32 + gj] = wv[i].y;
        Ws[(k + 2) * 32 + gj] = wv[i].z; Ws[(k + 3) * 32 + gj] = wv[i].w;
    }
    __syncthreads();
    for (int kt = 0; kt < 16; kt++) {
        int cur = kt & 1;
        if (kt < 15) {
#pragma unroll
            for (int i = 0; i < 4; i++)
                hv[i] = ldcg4(hT + ((kt + 1) * 1024 + i * 256 + tid) * 4);
#pragma unroll
            for (int i = 0; i < 2; i++)
                wv[i] = __ldg((const float4*)(wrow + (kt + 1) * 64 + i * 4));
        }
        const float* Hc = Hs + cur * (64 * 68);
        const float* Wc = Ws + cur * (64 * 32);
#pragma unroll 8
        for (int kk = 0; kk < 64; kk++) {
            float2 a = *(const float2*)&Hc[kk * 68 + r0];
            ulonglong2 w = *(const ulonglong2*)&Wc[kk * 32 + tx * 4];  // LDS.128
            u64 a0 = pk2(a.x, a.x), a1 = pk2(a.y, a.y);
            FMA2(acc[0][0], a0, w.x); FMA2(acc[0][1], a0, w.y);
            FMA2(acc[1][0], a1, w.x); FMA2(acc[1][1], a1, w.y);
        }
        if (kt < 15) {
            float* Hn = Hs + (cur ^ 1) * (64 * 68);
            float* Wn = Ws + (cur ^ 1) * (64 * 32);
#pragma unroll
            for (int i = 0; i < 4; i++) {
                int f4 = i * 256 + tid;
                *(float4*)&Hn[(f4 >> 4) * 68 + (f4 & 15) * 4] = hv[i];
            }
#pragma unroll
            for (int i = 0; i < 2; i++) {
                int k = kq * 8 + i * 4;
                Wn[(k + 0) * 32 + gj] = wv[i].x; Wn[(k + 1) * 32 + gj] = wv[i].y;
                Wn[(k + 2) * 32 + gj] = wv[i].z; Wn[(k + 3) * 32 + gj] = wv[i].w;
            }
        }
        __syncthreads();
    }
}

// ---------------- persistent layer-1 -----------------------------------------
__global__ void __launch_bounds__(256, 1) k_l1_persist(
        const float* __restrict__ c02,
        const float* __restrict__ whh1, const float* __restrict__ wih2,
        const float* __restrict__ whh2,
        const float* __restrict__ bih2, const float* __restrict__ bhh2) {
    extern __shared__ float sm[];
    float* Ws = sm;                   // [2][64][32]
    float* Hs = sm + 2 * 64 * 32;     // [2][64][68]
    const int tid = threadIdx.x;
    const int j0 = blockIdx.x * 8;
    const int tx = tid & 7, r0 = (tid >> 3) * 2;
    const int jg = j0 + tx;

    float c2[2] = { c02[(r0 + 0) * H2 + jg], c02[(r0 + 1) * H2 + jg] };
    float bs[4];
#pragma unroll
    for (int g = 0; g < 4; g++) bs[g] = bih2[g * H2 + jg] + bhh2[g * H2 + jg];

    unsigned bt = 0;
    for (int t = 0; t < S; t++) {
        int p = t & 1;
        const float* h1prev = g_H1T + p * (H2 * Bz);
        float*       h1out  = g_H1T + (p ^ 1) * (H2 * Bz);
        const float* h2prev = g_H2T + p * (H2 * Bz);
        float*       h2out  = g_H2T + (p ^ 1) * (H2 * Bz);

        // ---- lstm1: whh1 @ h1prev, cell input = c2 (own cell discarded) ----
        u64 acc[2][2] = {{0ull, 0ull}, {0ull, 0ull}};
        l1_gemm(h1prev, whh1, j0, tid, acc, Hs, Ws);
        const float* pre = g_G1 + (size_t)t * Bz * G8;
#pragma unroll
        for (int r = 0; r < 2; r++) {
            int b = r0 + r;
            float2 if_ = upk2(acc[r][0]);
            float2 go_ = upk2(acc[r][1]);
            const float* pb = pre + (size_t)b * G8;
            float gi = if_.x + pb[0 * H2 + jg];
            float gf = if_.y + pb[1 * H2 + jg];
            float gg = go_.x + pb[2 * H2 + jg];
            float go = go_.y + pb[3 * H2 + jg];
            float cc = sigf(gf) * c2[r] + sigf(gi) * tanhf(gg);
            h1out[(size_t)jg * Bz + b] = sigf(go) * tanhf(cc);
        }
        // ---- lstm2 part A: whh2 @ h2prev (independent of h1out) ----
        acc[0][0] = acc[0][1] = acc[1][0] = acc[1][1] = 0ull;
        l1_gemm(h2prev, whh2, j0, tid, acc, Hs, Ws);
        bt += 128; gbar(&g_bar1, bt);            // h1out now globally visible
        // ---- lstm2 part B: wih2 @ h1new ----
        l1_gemm(h1out, wih2, j0, tid, acc, Hs, Ws);
#pragma unroll
        for (int r = 0; r < 2; r++) {
            int b = r0 + r;
            float2 if_ = upk2(acc[r][0]);
            float2 go_ = upk2(acc[r][1]);
            float gi = if_.x + bs[0];
            float gf = if_.y + bs[1];
            float gg = go_.x + bs[2];
            float go = go_.y + bs[3];
            float cn = sigf(gf) * c2[r] + sigf(gi) * tanhf(gg);
            c2[r] = cn;
            float h2v = sigf(go) * tanhf(cn);
            h2out[(size_t)jg * Bz + b] = h2v;
            if (t == S - 1) g_H2R[(size_t)b * H2 + jg] = h2v;
        }
        bt += 128; gbar(&g_bar1, bt);            // h2out visible for next step
    }
}

// ---------------- launch -----------------------------------------------------
extern "C" void kernel_launch(void* const* d_in, const int* in_sizes, int n_in,
                              void* d_out, int out_size) {
    const int*   x     = (const int*)  d_in[0];
    const float* emb   = (const float*)d_in[1];
    const float* h0f   = (const float*)d_in[2];
    const float* c0f   = (const float*)d_in[3];
    const float* h0b   = (const float*)d_in[4];
    const float* c0b   = (const float*)d_in[5];
    const float* h01   = (const float*)d_in[6];
    const float* h02   = (const float*)d_in[7];
    const float* c02   = (const float*)d_in[8];
    const float* wih_f = (const float*)d_in[9];
    const float* whh_f = (const float*)d_in[10];
    const float* bih_f = (const float*)d_in[11];
    const float* bhh_f = (const float*)d_in[12];
    const float* wih_b = (const float*)d_in[13];
    const float* whh_b = (const float*)d_in[14];
    const float* bih_b = (const float*)d_in[15];
    const float* bhh_b = (const float*)d_in[16];
    const float* wih1  = (const float*)d_in[17];
    const float* whh1  = (const float*)d_in[18];
    const float* bih1  = (const float*)d_in[19];
    const float* bhh1  = (const float*)d_in[20];
    const float* wih2  = (const float*)d_in[21];
    const float* whh2  = (const float*)d_in[22];
    const float* bih2  = (const float*)d_in[23];
    const float* bhh2  = (const float*)d_in[24];
    const float* wlin  = (const float*)d_in[25];
    const float* blin  = (const float*)d_in[26];
    float* out = (float*)d_out;

    float *pX, *pGF, *pGB, *pXIN, *pG1, *pH2R;
    cudaGetSymbolAddress((void**)&pX,   g_X);
    cudaGetSymbolAddress((void**)&pGF,  g_GF);
    cudaGetSymbolAddress((void**)&pGB,  g_GB);
    cudaGetSymbolAddress((void**)&pXIN, g_XIN);
    cudaGetSymbolAddress((void**)&pG1,  g_G1);
    cudaGetSymbolAddress((void**)&pH2R, g_H2R);

    const int L0_SM = (512 * 32 + 2 * 64 * 68) * 4;          // 100352 B
    const int L1_SM = (2 * 64 * 32 + 2 * 64 * 68) * 4;       // 51200 B
    cudaFuncSetAttribute(k_l0_persist, cudaFuncAttributeMaxDynamicSharedMemorySize, L0_SM);
    cudaFuncSetAttribute(k_l1_persist, cudaFuncAttributeMaxDynamicSharedMemorySize, L1_SM);

    // A: gather + init (also zeroes barrier counters each replay)
    k_embed<<<R, 128>>>(x, emb);
    k_init<<<768, 256>>>(h01, h02, h0f, h0b);

    // B: hoisted input-side gate GEMMs for layer 0
    k_gemm_bias<128><<<dim3(G4 / 64, R / 128), 256>>>(pX, wih_f, bih_f, bhh_f, pGF, H, G4);
    k_gemm_bias<128><<<dim3(G4 / 64, R / 128), 256>>>(pX, wih_b, bih_b, bhh_b, pGB, H, G4);

    // C: persistent bidirectional layer-0 recurrence (one launch)
    k_l0_persist<<<128, 256, L0_SM>>>(c0f, c0b, whh_f, whh_b);

    // D: hoisted input-side GEMM for lstm1
    k_gemm_bias<128><<<dim3(G8 / 64, R / 128), 256>>>(pXIN, wih1, bih1, bhh1, pG1, H2, G8);

    // E: persistent layer-1 recurrence (one launch)
    k_l1_persist<<<128, 256, L1_SM>>>(c02, whh1, wih2, whh2, bih2, bhh2);

    // F: logits
    k_gemm_bias<64><<<dim3(V / 64, 1), 256>>>(pH2R, wlin, blin, nullptr, out, H2, V);
}